// round 1
// baseline (speedup 1.0000x reference)
#include <cuda_runtime.h>
#include <math.h>

// Problem constants
#define TT 2048
#define BB 2
#define EE 1024
#define HH 8
#define DD 128
#define RR 2
#define NHASHB 8
#define CHUNKC 32
#define CC (TT/CHUNKC)   // 64
#define MW (3*CHUNKC)    // 96
#define MROWS (TT*BB)    // 4096

// -------------------- device scratch (no allocations allowed) --------------------
__device__ float g_qf[TT*BB*EE];        // 16 MB : query @ Wq + bq
__device__ float g_vf[TT*BB*EE];        // 16 MB : value @ Wv + bv
__device__ float g_ctx[TT*BB*EE];       // 16 MB : combined context pre-Wo
__device__ float g_invnorm[TT*BB];      // 1/||qf|| per token
__device__ int   g_hash[BB*RR*HH*TT];   // hash bucket per (b,r,h,t)
__device__ int   g_perm[BB*RR*HH*TT];   // stable sort permutation (sorted pos -> t)
__device__ int   g_inv [BB*RR*HH*TT];   // inverse permutation (t -> sorted pos)
__device__ float g_o[RR*BB*HH*TT*DD];   // 33.5 MB per-round attention output (original token order)
__device__ float g_z[RR*BB*HH*TT];      // per-round logsumexp (original token order)

// -------------------- GEMM: out[M,N] = A[M,K] @ W[K,N] + bias --------------------
// M=4096, N=K=1024. 64x64 tile, 256 threads, 4x4 per thread.
__global__ void __launch_bounds__(256) gemm_bias_kernel(
    const float* __restrict__ A, const float* __restrict__ W,
    const float* __restrict__ bias, float* __restrict__ out)
{
    const int N = 1024, K = 1024;
    const int bm = blockIdx.y * 64;
    const int bn = blockIdx.x * 64;
    __shared__ float As[16][65];   // As[k][m], padded
    __shared__ float Bs[16][68];   // Bs[k][n], padded
    const int tid = threadIdx.x;
    const int tx = tid & 15, ty = tid >> 4;
    float acc[4][4] = {};
    for (int k0 = 0; k0 < K; k0 += 16) {
        #pragma unroll
        for (int i = 0; i < 4; i++) {
            int idx = tid + i*256;           // 0..1023
            int m = idx >> 4, kk = idx & 15;
            As[kk][m] = A[(bm+m)*K + k0 + kk];
        }
        #pragma unroll
        for (int i = 0; i < 4; i++) {
            int idx = tid + i*256;
            int kk = idx >> 6, n = idx & 63;
            Bs[kk][n] = W[(k0+kk)*N + bn + n];
        }
        __syncthreads();
        #pragma unroll
        for (int kk = 0; kk < 16; kk++) {
            float ra[4], rb[4];
            #pragma unroll
            for (int i = 0; i < 4; i++) ra[i] = As[kk][ty*4+i];
            #pragma unroll
            for (int j = 0; j < 4; j++) rb[j] = Bs[kk][tx*4+j];
            #pragma unroll
            for (int i = 0; i < 4; i++)
                #pragma unroll
                for (int j = 0; j < 4; j++)
                    acc[i][j] += ra[i]*rb[j];
        }
        __syncthreads();
    }
    #pragma unroll
    for (int i = 0; i < 4; i++) {
        int m = bm + ty*4 + i;
        #pragma unroll
        for (int j = 0; j < 4; j++) {
            int n = bn + tx*4 + j;
            out[m*N + n] = acc[i][j] + bias[n];
        }
    }
}

// -------------------- norm + hash --------------------
// One block per token (t,b). Computes 1/||qf||_E and the R*H hash buckets.
// Hashing is scale-invariant, so we hash raw qf once (q_hash == k_hash).
__global__ void __launch_bounds__(128) norm_hash_kernel(const float* __restrict__ hw)
{
    int tb = blockIdx.x;                  // tb = t*B + b
    int t = tb >> 1, b = tb & 1;
    const float* row = g_qf + tb*EE;
    int tid = threadIdx.x, lane = tid & 31, wp = tid >> 5;

    float ss = 0.f;
    for (int i = tid; i < EE; i += 128) { float x = row[i]; ss += x*x; }
    #pragma unroll
    for (int o = 16; o; o >>= 1) ss += __shfl_xor_sync(0xffffffffu, ss, o);
    __shared__ float wred[4];
    if (lane == 0) wred[wp] = ss;
    __syncthreads();
    if (tid == 0) {
        float tot = wred[0]+wred[1]+wred[2]+wred[3];
        g_invnorm[tb] = 1.0f / sqrtf(tot);
    }

    // 64 (r,h,n) dot products, 16 per warp
    __shared__ float s_lin[64];
    for (int i = 0; i < 16; i++) {
        int co = wp*16 + i;               // co = ((r*8+h)*4 + n)
        int n = co & 3, h = (co >> 2) & 7, r = co >> 5;
        float s = 0.f;
        const float* x = row + h*DD;
        const float* w = hw + ((r*HH + h)*DD)*4 + n;
        for (int d = lane; d < DD; d += 32)
            s += x[d] * w[d*4];
        #pragma unroll
        for (int o = 16; o; o >>= 1) s += __shfl_xor_sync(0xffffffffu, s, o);
        if (lane == 0) s_lin[co] = s;
    }
    __syncthreads();
    if (tid < 16) {
        int r = tid >> 3, h = tid & 7;
        const float* L = s_lin + (r*8 + h)*4;
        float best = L[0]; int bi = 0;
        #pragma unroll
        for (int j = 1; j < 8; j++) {
            float v = (j < 4) ? L[j] : -L[j-4];
            if (v > best) { best = v; bi = j; }   // strict > : first max wins (jnp.argmax)
        }
        g_hash[((b*RR + r)*HH + h)*TT + t] = bi;
    }
}

// -------------------- stable counting sort per (b,r,h) --------------------
__global__ void __launch_bounds__(256) sort_kernel()
{
    int brh = blockIdx.x;                 // (b*R + r)*H + h
    const int* hs = g_hash + brh*TT;
    int* pp = g_perm + brh*TT;
    int* iv = g_inv  + brh*TT;
    __shared__ int hist[256][8];
    __shared__ int binbase[8];
    int tid = threadIdx.x;
    int base = tid*8;
    int myh[8];
    int loc[8] = {0,0,0,0,0,0,0,0};
    #pragma unroll
    for (int i = 0; i < 8; i++) { int v = hs[base+i]; myh[i] = v; loc[v]++; }
    #pragma unroll
    for (int v = 0; v < 8; v++) hist[tid][v] = loc[v];
    __syncthreads();
    if (tid < 8) {                        // exclusive scan over threads per bin
        int s = 0;
        for (int j = 0; j < 256; j++) { int c = hist[j][tid]; hist[j][tid] = s; s += c; }
        binbase[tid] = s;                 // bin total (temporarily)
    }
    __syncthreads();
    if (tid == 0) {                       // exclusive scan over bins
        int s = 0;
        for (int v = 0; v < 8; v++) { int t0 = binbase[v]; binbase[v] = s; s += t0; }
    }
    __syncthreads();
    int off[8];
    #pragma unroll
    for (int v = 0; v < 8; v++) off[v] = binbase[v] + hist[tid][v];
    #pragma unroll
    for (int i = 0; i < 8; i++) {         // in t order -> stable
        int v = myh[i];
        int pos = off[v]++;
        pp[pos] = base + i;
        iv[base + i] = pos;
    }
}

// -------------------- chunked LSH attention --------------------
// One block per (b,r,h,c). 128 threads = 4 warps; warp handles 8 query rows.
__global__ void __launch_bounds__(128) attn_kernel()
{
    extern __shared__ float sm[];
    float* q_s = sm;                      // 32 x 129
    float* k_s = sm + 32*129;             // 96 x 129
    float* v_s = k_s + 96*129;            // 96 x 129
    __shared__ int s_qid[32], s_kid[96], s_qh[32], s_kh[96];
    __shared__ int s_cq[64], s_ck[192];
    __shared__ float s_kinv[96];

    int bid = blockIdx.x;
    int c = bid & 63;
    int h = (bid >> 6) & 7;
    int r = (bid >> 9) & 1;
    int b = bid >> 10;
    int brh = (b*RR + r)*HH + h;
    const int* pp = g_perm + brh*TT;
    int tid = threadIdx.x, lane = tid & 31, wp = tid >> 5;

    if (tid < 32) {
        int qid = pp[c*32 + tid];
        s_qid[tid] = qid;
        s_qh[tid] = g_hash[brh*TT + qid];
        s_cq[tid*2+0] = g_inv[((b*RR+0)*HH+h)*TT + qid] >> 5;
        s_cq[tid*2+1] = g_inv[((b*RR+1)*HH+h)*TT + qid] >> 5;
    }
    if (tid < 96) {
        int cc = (c + (tid >> 5) + CC - 1) & (CC - 1);   // chunks c-1, c, c+1 (wraparound)
        int kid = pp[cc*32 + (tid & 31)];
        s_kid[tid] = kid;
        s_kh[tid] = g_hash[brh*TT + kid];
        s_kinv[tid] = g_invnorm[kid*BB + b];
        s_ck[tid*2+0] = g_inv[((b*RR+0)*HH+h)*TT + kid] >> 5;
        s_ck[tid*2+1] = g_inv[((b*RR+1)*HH+h)*TT + kid] >> 5;
    }
    __syncthreads();

    const float scale = 0.08838834764831845f;  // 128^-0.5
    for (int idx = tid; idx < 32*128; idx += 128) {
        int l = idx >> 7, d = idx & 127;
        q_s[l*129 + d] = g_qf[(s_qid[l]*BB + b)*EE + h*DD + d] * scale;
    }
    for (int idx = tid; idx < 96*128; idx += 128) {
        int j = idx >> 7, d = idx & 127;
        int gbase = (s_kid[j]*BB + b)*EE + h*DD + d;
        k_s[j*129 + d] = g_qf[gbase] * s_kinv[j];
        v_s[j*129 + d] = g_vf[gbase];
    }
    __syncthreads();

    for (int li = 0; li < 8; li++) {
        int l = wp*8 + li;
        // ---- QK^T : each lane owns keys m = lane, lane+32, lane+64
        float a0 = 0.f, a1 = 0.f, a2 = 0.f;
        const float* qrow = q_s + l*129;
        const float* k0 = k_s + lane*129;
        const float* k1 = k_s + (lane+32)*129;
        const float* k2 = k_s + (lane+64)*129;
        #pragma unroll 8
        for (int d = 0; d < 128; d++) {
            float qv = qrow[d];
            a0 += qv*k0[d]; a1 += qv*k1[d]; a2 += qv*k2[d];
        }
        // ---- masks + duplicate-count correction
        int qh = s_qh[l], qid = s_qid[l];
        int cq0 = s_cq[l*2], cq1 = s_cq[l*2+1];
        float sc[3] = {a0, a1, a2};
        #pragma unroll
        for (int mi = 0; mi < 3; mi++) {
            int m = mi*32 + lane;
            float s = sc[mi];
            if (qh != s_kh[m])   s -= 1.0e16f;    // mask_different_hashes
            if (qid == s_kid[m]) s -= 1.0e8f;     // mask_current
            int d0 = (s_ck[m*2+0] - cq0) & (CC-1);
            int d1 = (s_ck[m*2+1] - cq1) & (CC-1);
            int dup = ((d0 <= 1) | (d0 == CC-1)) + ((d1 <= 1) | (d1 == CC-1));
            if (dup == 2) s -= 0.6931471805599453f;   // log(2); dup==1 -> log(1)=0
            sc[mi] = s;
        }
        // ---- softmax over the 96-key window (row spread across lanes)
        float mx = fmaxf(sc[0], fmaxf(sc[1], sc[2]));
        #pragma unroll
        for (int o = 16; o; o >>= 1) mx = fmaxf(mx, __shfl_xor_sync(0xffffffffu, mx, o));
        float p0 = expf(sc[0]-mx), p1 = expf(sc[1]-mx), p2 = expf(sc[2]-mx);
        float sum = p0 + p1 + p2;
        #pragma unroll
        for (int o = 16; o; o >>= 1) sum += __shfl_xor_sync(0xffffffffu, sum, o);
        float zval = logf(sum) + mx;
        float rinv = 1.0f / sum;
        // ---- P @ V : lanes own d = lane + {0,32,64,96}
        float o0 = 0.f, o1 = 0.f, o2 = 0.f, o3 = 0.f;
        float pr[3] = {p0, p1, p2};
        #pragma unroll
        for (int mi = 0; mi < 3; mi++) {
            #pragma unroll
            for (int src = 0; src < 32; src++) {
                float pv = __shfl_sync(0xffffffffu, pr[mi], src);
                const float* vr = v_s + (mi*32 + src)*129;
                o0 += pv*vr[lane];
                o1 += pv*vr[lane+32];
                o2 += pv*vr[lane+64];
                o3 += pv*vr[lane+96];
            }
        }
        // scatter back to original token order (qid unique per block row)
        float* op = g_o + (((r*BB + b)*HH + h)*TT + qid)*DD;
        op[lane]      = o0*rinv;
        op[lane+32]   = o1*rinv;
        op[lane+64]   = o2*rinv;
        op[lane+96]   = o3*rinv;
        if (lane == 0) g_z[((r*BB + b)*HH + h)*TT + qid] = zval;
    }
}

// -------------------- round combination --------------------
__global__ void __launch_bounds__(256) combine_kernel()
{
    int idx = blockIdx.x*256 + threadIdx.x;    // over B*H*T*D = 2^22
    int d = idx & 127;
    int t = (idx >> 7) & 2047;
    int h = (idx >> 18) & 7;
    int b = idx >> 21;
    int zi = (b*HH + h)*TT + t;
    float z0 = g_z[zi];
    float z1 = g_z[BB*HH*TT + zi];
    float mz = fmaxf(z0, z1);
    float e0 = expf(z0 - mz), e1 = expf(z1 - mz);
    float winv = 1.0f / (e0 + e1);
    int oi = ((b*HH + h)*TT + t)*DD + d;
    float o0 = g_o[oi];
    float o1 = g_o[BB*HH*TT*DD + oi];
    g_ctx[(t*BB + b)*EE + h*DD + d] = (e0*o0 + e1*o1) * winv;
}

// -------------------- launch --------------------
extern "C" void kernel_launch(void* const* d_in, const int* in_sizes, int n_in,
                              void* d_out, int out_size)
{
    const float* query = (const float*)d_in[0];
    // d_in[1] = key, unused (share_kq)
    const float* value = (const float*)d_in[2];
    const float* Wq = (const float*)d_in[3];
    const float* bq = (const float*)d_in[4];
    const float* Wv = (const float*)d_in[5];
    const float* bv = (const float*)d_in[6];
    const float* Wo = (const float*)d_in[7];
    const float* bo = (const float*)d_in[8];
    const float* hw = (const float*)d_in[9];

    float* qf;  cudaGetSymbolAddress((void**)&qf,  g_qf);
    float* vf;  cudaGetSymbolAddress((void**)&vf,  g_vf);
    float* ctx; cudaGetSymbolAddress((void**)&ctx, g_ctx);

    const int ATTN_SMEM = (32*129 + 96*129 + 96*129) * (int)sizeof(float);  // 115584 B
    cudaFuncSetAttribute(attn_kernel, cudaFuncAttributeMaxDynamicSharedMemorySize, ATTN_SMEM);

    dim3 gemm_grid(16, 64);   // N/64, M/64

    gemm_bias_kernel<<<gemm_grid, 256>>>(query, Wq, bq, qf);
    gemm_bias_kernel<<<gemm_grid, 256>>>(value, Wv, bv, vf);
    norm_hash_kernel<<<TT*BB, 128>>>(hw);
    sort_kernel<<<BB*RR*HH, 256>>>();
    attn_kernel<<<BB*RR*HH*CC, 128, ATTN_SMEM>>>();
    combine_kernel<<<(BB*HH*TT*DD)/256, 256>>>();
    gemm_bias_kernel<<<gemm_grid, 256>>>(ctx, Wo, bo, (float*)d_out);
}

// round 3
// speedup vs baseline: 1.1557x; 1.1557x over previous
#include <cuda_runtime.h>
#include <math.h>
#include <stdint.h>

// Problem constants
#define TT 2048
#define BB 2
#define EE 1024
#define HH 8
#define DD 128
#define RR 2
#define CHUNKC 32
#define CC (TT/CHUNKC)   // 64
#define KTOT 1024
#define NTOT 1024

// -------------------- device scratch --------------------
__device__ float g_qf[TT*BB*EE];
__device__ float g_vf[TT*BB*EE];
__device__ float g_ctx[TT*BB*EE];
__device__ float g_invnorm[TT*BB];
__device__ int   g_hash[BB*RR*HH*TT];
__device__ int   g_perm[BB*RR*HH*TT];
__device__ int   g_inv [BB*RR*HH*TT];
__device__ float g_o[RR*BB*HH*TT*DD];
__device__ float g_z[RR*BB*HH*TT];

// ==================== SGEMM: out[M,N] = A[M,K] @ W[K,N] + bias ====================
// 128x128 CTA tile, 256 threads, 8x8 per thread, K-step 16, double-buffered smem.
// gridDim.z selects between two (A, W, bias, out) problem sets (fused launches).
#define KS 16
#define NST (KTOT/KS)   // 64

__global__ void __launch_bounds__(256, 2) sgemm_kernel(
    const float* __restrict__ A0, const float* __restrict__ W0,
    const float* __restrict__ b0, float* __restrict__ o0,
    const float* __restrict__ A1, const float* __restrict__ W1,
    const float* __restrict__ b1, float* __restrict__ o1)
{
    const float* A    = blockIdx.z ? A1 : A0;
    const float* W    = blockIdx.z ? W1 : W0;
    const float* bias = blockIdx.z ? b1 : b0;
    float*       out  = blockIdx.z ? o1 : o0;

    __shared__ float As[2][KS][132];   // [k][m], padded
    __shared__ float Bs[2][KS][128];   // [k][n]
    __shared__ float bsm[128];

    const int tid = threadIdx.x;
    const int bm = blockIdx.y * 128;
    const int bn = blockIdx.x * 128;
    const int tx = tid & 15;           // n quadrant
    const int ty = tid >> 4;           // m quadrant

    if (tid < 128) bsm[tid] = bias[bn + tid];

    // A tile load mapping: 128 rows x 16 k = 512 float4; 2 per thread
    const int arow = tid >> 2;         // 0..63
    const int akq  = tid & 3;          // which float4 within the 16-k row
    // B tile load mapping: 16 k-rows x 128 n = 512 float4; 2 per thread
    const int bkr = tid >> 5;          // 0..7
    const int bn4 = tid & 31;          // float4 column

    const float* Ap0 = A + (size_t)(bm + arow) * KTOT + akq * 4;
    const float* Ap1 = A + (size_t)(bm + 64 + arow) * KTOT + akq * 4;
    const float* Wp0 = W + (size_t)bkr * NTOT + bn + bn4 * 4;
    const float* Wp1 = W + (size_t)(8 + bkr) * NTOT + bn + bn4 * 4;

    float4 pa0, pa1, pb0, pb1;
    float acc[8][8] = {};

    // preload stage 0
    pa0 = *(const float4*)(Ap0);
    pa1 = *(const float4*)(Ap1);
    pb0 = *(const float4*)(Wp0);
    pb1 = *(const float4*)(Wp1);
    {
        const int kb = akq * 4;
        As[0][kb+0][arow]    = pa0.x; As[0][kb+1][arow]    = pa0.y;
        As[0][kb+2][arow]    = pa0.z; As[0][kb+3][arow]    = pa0.w;
        As[0][kb+0][64+arow] = pa1.x; As[0][kb+1][64+arow] = pa1.y;
        As[0][kb+2][64+arow] = pa1.z; As[0][kb+3][64+arow] = pa1.w;
        *(float4*)&Bs[0][bkr][bn4*4]   = pb0;
        *(float4*)&Bs[0][8+bkr][bn4*4] = pb1;
    }
    __syncthreads();

    for (int s = 0; s < NST; s++) {
        const int buf = s & 1;
        if (s + 1 < NST) {
            const size_t ko = (size_t)(s + 1) * KS;
            pa0 = *(const float4*)(Ap0 + ko);
            pa1 = *(const float4*)(Ap1 + ko);
            pb0 = *(const float4*)(Wp0 + ko * NTOT);
            pb1 = *(const float4*)(Wp1 + ko * NTOT);
        }
        #pragma unroll
        for (int k = 0; k < KS; k++) {
            float4 a0 = *(const float4*)&As[buf][k][ty*4];
            float4 a1 = *(const float4*)&As[buf][k][64 + ty*4];
            float4 bv0 = *(const float4*)&Bs[buf][k][tx*4];
            float4 bv1 = *(const float4*)&Bs[buf][k][64 + tx*4];
            float av[8] = {a0.x,a0.y,a0.z,a0.w,a1.x,a1.y,a1.z,a1.w};
            float bw[8] = {bv0.x,bv0.y,bv0.z,bv0.w,bv1.x,bv1.y,bv1.z,bv1.w};
            #pragma unroll
            for (int i = 0; i < 8; i++)
                #pragma unroll
                for (int j = 0; j < 8; j++)
                    acc[i][j] += av[i] * bw[j];
        }
        if (s + 1 < NST) {
            const int nb = buf ^ 1;
            __syncthreads();
            const int kb = akq * 4;
            As[nb][kb+0][arow]    = pa0.x; As[nb][kb+1][arow]    = pa0.y;
            As[nb][kb+2][arow]    = pa0.z; As[nb][kb+3][arow]    = pa0.w;
            As[nb][kb+0][64+arow] = pa1.x; As[nb][kb+1][64+arow] = pa1.y;
            As[nb][kb+2][64+arow] = pa1.z; As[nb][kb+3][64+arow] = pa1.w;
            *(float4*)&Bs[nb][bkr][bn4*4]   = pb0;
            *(float4*)&Bs[nb][8+bkr][bn4*4] = pb1;
            __syncthreads();
        }
    }

    // epilogue: 8 rows x 8 cols per thread, two float4 stores per row
    #pragma unroll
    for (int i = 0; i < 8; i++) {
        const int m = bm + ((i < 4) ? (ty*4 + i) : (64 + ty*4 + i - 4));
        float* orow = out + (size_t)m * NTOT + bn;
        const int n0 = tx*4, n1 = 64 + tx*4;
        float4 r0, r1;
        r0.x = acc[i][0] + bsm[n0+0]; r0.y = acc[i][1] + bsm[n0+1];
        r0.z = acc[i][2] + bsm[n0+2]; r0.w = acc[i][3] + bsm[n0+3];
        r1.x = acc[i][4] + bsm[n1+0]; r1.y = acc[i][5] + bsm[n1+1];
        r1.z = acc[i][6] + bsm[n1+2]; r1.w = acc[i][7] + bsm[n1+3];
        *(float4*)(orow + n0) = r0;
        *(float4*)(orow + n1) = r1;
    }
}

// ==================== norm + hash ====================
__global__ void __launch_bounds__(128) norm_hash_kernel(const float* __restrict__ hw)
{
    int tb = blockIdx.x;
    int t = tb >> 1, b = tb & 1;
    const float* row = g_qf + tb*EE;
    int tid = threadIdx.x, lane = tid & 31, wp = tid >> 5;

    float ss = 0.f;
    for (int i = tid; i < EE; i += 128) { float x = row[i]; ss += x*x; }
    #pragma unroll
    for (int o = 16; o; o >>= 1) ss += __shfl_xor_sync(0xffffffffu, ss, o);
    __shared__ float wred[4];
    if (lane == 0) wred[wp] = ss;
    __syncthreads();
    if (tid == 0) g_invnorm[tb] = 1.0f / sqrtf(wred[0]+wred[1]+wred[2]+wred[3]);

    __shared__ float s_lin[64];
    for (int i = 0; i < 16; i++) {
        int co = wp*16 + i;
        int n = co & 3, h = (co >> 2) & 7, r = co >> 5;
        float s = 0.f;
        const float* x = row + h*DD;
        const float* w = hw + ((r*HH + h)*DD)*4 + n;
        for (int d = lane; d < DD; d += 32) s += x[d] * w[d*4];
        #pragma unroll
        for (int o = 16; o; o >>= 1) s += __shfl_xor_sync(0xffffffffu, s, o);
        if (lane == 0) s_lin[co] = s;
    }
    __syncthreads();
    if (tid < 16) {
        int r = tid >> 3, h = tid & 7;
        const float* L = s_lin + (r*8 + h)*4;
        float best = L[0]; int bi = 0;
        #pragma unroll
        for (int j = 1; j < 8; j++) {
            float v = (j < 4) ? L[j] : -L[j-4];
            if (v > best) { best = v; bi = j; }
        }
        g_hash[((b*RR + r)*HH + h)*TT + t] = bi;
    }
}

// ==================== stable counting sort ====================
__global__ void __launch_bounds__(256) sort_kernel()
{
    int brh = blockIdx.x;
    const int* hs = g_hash + brh*TT;
    int* pp = g_perm + brh*TT;
    int* iv = g_inv  + brh*TT;
    __shared__ int hist[256][8];
    __shared__ int binbase[8];
    int tid = threadIdx.x;
    int base = tid*8;
    int myh[8];
    int loc[8] = {0,0,0,0,0,0,0,0};
    #pragma unroll
    for (int i = 0; i < 8; i++) { int v = hs[base+i]; myh[i] = v; loc[v]++; }
    #pragma unroll
    for (int v = 0; v < 8; v++) hist[tid][v] = loc[v];
    __syncthreads();
    if (tid < 8) {
        int s = 0;
        for (int j = 0; j < 256; j++) { int c = hist[j][tid]; hist[j][tid] = s; s += c; }
        binbase[tid] = s;
    }
    __syncthreads();
    if (tid == 0) {
        int s = 0;
        for (int v = 0; v < 8; v++) { int t0 = binbase[v]; binbase[v] = s; s += t0; }
    }
    __syncthreads();
    int off[8];
    #pragma unroll
    for (int v = 0; v < 8; v++) off[v] = binbase[v] + hist[tid][v];
    #pragma unroll
    for (int i = 0; i < 8; i++) {
        int v = myh[i];
        int pos = off[v]++;
        pp[pos] = base + i;
        iv[base + i] = pos;
    }
}

// ==================== chunked LSH attention ====================
__global__ void __launch_bounds__(128) attn_kernel()
{
    extern __shared__ float sm[];
    float* q_s = sm;
    float* k_s = sm + 32*129;
    float* v_s = k_s + 96*129;
    __shared__ int s_qid[32], s_kid[96], s_qh[32], s_kh[96];
    __shared__ int s_cq[64], s_ck[192];
    __shared__ float s_kinv[96];

    int bid = blockIdx.x;
    int c = bid & 63;
    int h = (bid >> 6) & 7;
    int r = (bid >> 9) & 1;
    int b = bid >> 10;
    int brh = (b*RR + r)*HH + h;
    const int* pp = g_perm + brh*TT;
    int tid = threadIdx.x, lane = tid & 31, wp = tid >> 5;

    if (tid < 32) {
        int qid = pp[c*32 + tid];
        s_qid[tid] = qid;
        s_qh[tid] = g_hash[brh*TT + qid];
        s_cq[tid*2+0] = g_inv[((b*RR+0)*HH+h)*TT + qid] >> 5;
        s_cq[tid*2+1] = g_inv[((b*RR+1)*HH+h)*TT + qid] >> 5;
    }
    if (tid < 96) {
        int cc = (c + (tid >> 5) + CC - 1) & (CC - 1);
        int kid = pp[cc*32 + (tid & 31)];
        s_kid[tid] = kid;
        s_kh[tid] = g_hash[brh*TT + kid];
        s_kinv[tid] = g_invnorm[kid*BB + b];
        s_ck[tid*2+0] = g_inv[((b*RR+0)*HH+h)*TT + kid] >> 5;
        s_ck[tid*2+1] = g_inv[((b*RR+1)*HH+h)*TT + kid] >> 5;
    }
    __syncthreads();

    const float scale = 0.08838834764831845f;
    for (int idx = tid; idx < 32*128; idx += 128) {
        int l = idx >> 7, d = idx & 127;
        q_s[l*129 + d] = g_qf[(s_qid[l]*BB + b)*EE + h*DD + d] * scale;
    }
    for (int idx = tid; idx < 96*128; idx += 128) {
        int j = idx >> 7, d = idx & 127;
        int gbase = (s_kid[j]*BB + b)*EE + h*DD + d;
        k_s[j*129 + d] = g_qf[gbase] * s_kinv[j];
        v_s[j*129 + d] = g_vf[gbase];
    }
    __syncthreads();

    for (int li = 0; li < 8; li++) {
        int l = wp*8 + li;
        float a0 = 0.f, a1 = 0.f, a2 = 0.f;
        const float* qrow = q_s + l*129;
        const float* k0 = k_s + lane*129;
        const float* k1 = k_s + (lane+32)*129;
        const float* k2 = k_s + (lane+64)*129;
        #pragma unroll 8
        for (int d = 0; d < 128; d++) {
            float qv = qrow[d];
            a0 += qv*k0[d]; a1 += qv*k1[d]; a2 += qv*k2[d];
        }
        int qh = s_qh[l], qid = s_qid[l];
        int cq0 = s_cq[l*2], cq1 = s_cq[l*2+1];
        float sc[3] = {a0, a1, a2};
        #pragma unroll
        for (int mi = 0; mi < 3; mi++) {
            int m = mi*32 + lane;
            float s = sc[mi];
            if (qh != s_kh[m])   s -= 1.0e16f;
            if (qid == s_kid[m]) s -= 1.0e8f;
            int d0 = (s_ck[m*2+0] - cq0) & (CC-1);
            int d1 = (s_ck[m*2+1] - cq1) & (CC-1);
            int dup = ((d0 <= 1) | (d0 == CC-1)) + ((d1 <= 1) | (d1 == CC-1));
            if (dup == 2) s -= 0.6931471805599453f;
            sc[mi] = s;
        }
        float mx = fmaxf(sc[0], fmaxf(sc[1], sc[2]));
        #pragma unroll
        for (int o = 16; o; o >>= 1) mx = fmaxf(mx, __shfl_xor_sync(0xffffffffu, mx, o));
        float p0 = expf(sc[0]-mx), p1 = expf(sc[1]-mx), p2 = expf(sc[2]-mx);
        float sum = p0 + p1 + p2;
        #pragma unroll
        for (int o = 16; o; o >>= 1) sum += __shfl_xor_sync(0xffffffffu, sum, o);
        float zval = logf(sum) + mx;
        float rinv = 1.0f / sum;
        float o0 = 0.f, o1 = 0.f, o2 = 0.f, o3 = 0.f;
        float pr[3] = {p0, p1, p2};
        #pragma unroll
        for (int mi = 0; mi < 3; mi++) {
            #pragma unroll
            for (int src = 0; src < 32; src++) {
                float pv = __shfl_sync(0xffffffffu, pr[mi], src);
                const float* vr = v_s + (mi*32 + src)*129;
                o0 += pv*vr[lane];
                o1 += pv*vr[lane+32];
                o2 += pv*vr[lane+64];
                o3 += pv*vr[lane+96];
            }
        }
        float* op = g_o + (((r*BB + b)*HH + h)*TT + qid)*DD;
        op[lane]      = o0*rinv;
        op[lane+32]   = o1*rinv;
        op[lane+64]   = o2*rinv;
        op[lane+96]   = o3*rinv;
        if (lane == 0) g_z[((r*BB + b)*HH + h)*TT + qid] = zval;
    }
}

// ==================== round combination ====================
__global__ void __launch_bounds__(256) combine_kernel()
{
    int idx = blockIdx.x*256 + threadIdx.x;
    int d = idx & 127;
    int t = (idx >> 7) & 2047;
    int h = (idx >> 18) & 7;
    int b = idx >> 21;
    int zi = (b*HH + h)*TT + t;
    float z0 = g_z[zi];
    float z1 = g_z[BB*HH*TT + zi];
    float mz = fmaxf(z0, z1);
    float e0 = expf(z0 - mz), e1 = expf(z1 - mz);
    float winv = 1.0f / (e0 + e1);
    int oi = ((b*HH + h)*TT + t)*DD + d;
    float o0 = g_o[oi];
    float o1 = g_o[BB*HH*TT*DD + oi];
    g_ctx[(t*BB + b)*EE + h*DD + d] = (e0*o0 + e1*o1) * winv;
}

// ==================== launch ====================
extern "C" void kernel_launch(void* const* d_in, const int* in_sizes, int n_in,
                              void* d_out, int out_size)
{
    const float* query = (const float*)d_in[0];
    const float* value = (const float*)d_in[2];
    const float* Wq = (const float*)d_in[3];
    const float* bq = (const float*)d_in[4];
    const float* Wv = (const float*)d_in[5];
    const float* bv = (const float*)d_in[6];
    const float* Wo = (const float*)d_in[7];
    const float* bo = (const float*)d_in[8];
    const float* hw = (const float*)d_in[9];

    float* qf;  cudaGetSymbolAddress((void**)&qf,  g_qf);
    float* vf;  cudaGetSymbolAddress((void**)&vf,  g_vf);
    float* ctx; cudaGetSymbolAddress((void**)&ctx, g_ctx);

    const int ATTN_SMEM = (32*129 + 96*129 + 96*129) * (int)sizeof(float);
    cudaFuncSetAttribute(attn_kernel, cudaFuncAttributeMaxDynamicSharedMemorySize, ATTN_SMEM);

    dim3 gqv(NTOT/128, (TT*BB)/128, 2);   // fused Wq + Wv projections
    dim3 go (NTOT/128, (TT*BB)/128, 1);   // Wo projection

    sgemm_kernel<<<gqv, 256>>>(query, Wq, bq, qf, value, Wv, bv, vf);
    norm_hash_kernel<<<TT*BB, 128>>>(hw);
    sort_kernel<<<BB*RR*HH, 256>>>();
    attn_kernel<<<BB*RR*HH*CC, 128, ATTN_SMEM>>>();
    combine_kernel<<<(BB*HH*TT*DD)/256, 256>>>();
    sgemm_kernel<<<go, 256>>>(ctx, Wo, bo, (float*)d_out,
                              ctx, Wo, bo, (float*)d_out);
}

// round 4
// speedup vs baseline: 1.9575x; 1.6938x over previous
#include <cuda_runtime.h>
#include <math.h>
#include <stdint.h>

// Problem constants
#define TT 2048
#define BB 2
#define EE 1024
#define HH 8
#define DD 128
#define RR 2
#define CHUNKC 32
#define CC (TT/CHUNKC)   // 64
#define KTOT 1024
#define NTOT 1024

// -------------------- device scratch --------------------
__device__ float g_qf[TT*BB*EE];
__device__ float g_vf[TT*BB*EE];
__device__ float g_ctx[TT*BB*EE];
__device__ float g_invnorm[TT*BB];
__device__ int   g_hash[BB*RR*HH*TT];
__device__ int   g_perm[BB*RR*HH*TT];
__device__ int   g_inv [BB*RR*HH*TT];
__device__ float g_o[RR*BB*HH*TT*DD];
__device__ float g_z[RR*BB*HH*TT];

// ==================== SGEMM: out[M,N] = A[M,K] @ W[K,N] + bias ====================
#define KS 16
#define NST (KTOT/KS)   // 64

__global__ void __launch_bounds__(256, 2) sgemm_kernel(
    const float* __restrict__ A0, const float* __restrict__ W0,
    const float* __restrict__ b0, float* __restrict__ o0,
    const float* __restrict__ A1, const float* __restrict__ W1,
    const float* __restrict__ b1, float* __restrict__ o1)
{
    const float* A    = blockIdx.z ? A1 : A0;
    const float* W    = blockIdx.z ? W1 : W0;
    const float* bias = blockIdx.z ? b1 : b0;
    float*       out  = blockIdx.z ? o1 : o0;

    __shared__ float As[2][KS][132];
    __shared__ float Bs[2][KS][128];
    __shared__ float bsm[128];

    const int tid = threadIdx.x;
    const int bm = blockIdx.y * 128;
    const int bn = blockIdx.x * 128;
    const int tx = tid & 15;
    const int ty = tid >> 4;

    if (tid < 128) bsm[tid] = bias[bn + tid];

    const int arow = tid >> 2;
    const int akq  = tid & 3;
    const int bkr = tid >> 5;
    const int bn4 = tid & 31;

    const float* Ap0 = A + (size_t)(bm + arow) * KTOT + akq * 4;
    const float* Ap1 = A + (size_t)(bm + 64 + arow) * KTOT + akq * 4;
    const float* Wp0 = W + (size_t)bkr * NTOT + bn + bn4 * 4;
    const float* Wp1 = W + (size_t)(8 + bkr) * NTOT + bn + bn4 * 4;

    float4 pa0, pa1, pb0, pb1;
    float acc[8][8] = {};

    pa0 = *(const float4*)(Ap0);
    pa1 = *(const float4*)(Ap1);
    pb0 = *(const float4*)(Wp0);
    pb1 = *(const float4*)(Wp1);
    {
        const int kb = akq * 4;
        As[0][kb+0][arow]    = pa0.x; As[0][kb+1][arow]    = pa0.y;
        As[0][kb+2][arow]    = pa0.z; As[0][kb+3][arow]    = pa0.w;
        As[0][kb+0][64+arow] = pa1.x; As[0][kb+1][64+arow] = pa1.y;
        As[0][kb+2][64+arow] = pa1.z; As[0][kb+3][64+arow] = pa1.w;
        *(float4*)&Bs[0][bkr][bn4*4]   = pb0;
        *(float4*)&Bs[0][8+bkr][bn4*4] = pb1;
    }
    __syncthreads();

    for (int s = 0; s < NST; s++) {
        const int buf = s & 1;
        if (s + 1 < NST) {
            const size_t ko = (size_t)(s + 1) * KS;
            pa0 = *(const float4*)(Ap0 + ko);
            pa1 = *(const float4*)(Ap1 + ko);
            pb0 = *(const float4*)(Wp0 + ko * NTOT);
            pb1 = *(const float4*)(Wp1 + ko * NTOT);
        }
        #pragma unroll
        for (int k = 0; k < KS; k++) {
            float4 a0 = *(const float4*)&As[buf][k][ty*4];
            float4 a1 = *(const float4*)&As[buf][k][64 + ty*4];
            float4 bv0 = *(const float4*)&Bs[buf][k][tx*4];
            float4 bv1 = *(const float4*)&Bs[buf][k][64 + tx*4];
            float av[8] = {a0.x,a0.y,a0.z,a0.w,a1.x,a1.y,a1.z,a1.w};
            float bw[8] = {bv0.x,bv0.y,bv0.z,bv0.w,bv1.x,bv1.y,bv1.z,bv1.w};
            #pragma unroll
            for (int i = 0; i < 8; i++)
                #pragma unroll
                for (int j = 0; j < 8; j++)
                    acc[i][j] += av[i] * bw[j];
        }
        if (s + 1 < NST) {
            const int nb = buf ^ 1;
            __syncthreads();
            const int kb = akq * 4;
            As[nb][kb+0][arow]    = pa0.x; As[nb][kb+1][arow]    = pa0.y;
            As[nb][kb+2][arow]    = pa0.z; As[nb][kb+3][arow]    = pa0.w;
            As[nb][kb+0][64+arow] = pa1.x; As[nb][kb+1][64+arow] = pa1.y;
            As[nb][kb+2][64+arow] = pa1.z; As[nb][kb+3][64+arow] = pa1.w;
            *(float4*)&Bs[nb][bkr][bn4*4]   = pb0;
            *(float4*)&Bs[nb][8+bkr][bn4*4] = pb1;
            __syncthreads();
        }
    }

    #pragma unroll
    for (int i = 0; i < 8; i++) {
        const int m = bm + ((i < 4) ? (ty*4 + i) : (64 + ty*4 + i - 4));
        float* orow = out + (size_t)m * NTOT + bn;
        const int n0 = tx*4, n1 = 64 + tx*4;
        float4 r0, r1;
        r0.x = acc[i][0] + bsm[n0+0]; r0.y = acc[i][1] + bsm[n0+1];
        r0.z = acc[i][2] + bsm[n0+2]; r0.w = acc[i][3] + bsm[n0+3];
        r1.x = acc[i][4] + bsm[n1+0]; r1.y = acc[i][5] + bsm[n1+1];
        r1.z = acc[i][6] + bsm[n1+2]; r1.w = acc[i][7] + bsm[n1+3];
        *(float4*)(orow + n0) = r0;
        *(float4*)(orow + n1) = r1;
    }
}

// ==================== norm + hash ====================
__global__ void __launch_bounds__(128) norm_hash_kernel(const float* __restrict__ hw)
{
    int tb = blockIdx.x;
    int t = tb >> 1, b = tb & 1;
    const float* row = g_qf + tb*EE;
    int tid = threadIdx.x, lane = tid & 31, wp = tid >> 5;

    float ss = 0.f;
    for (int i = tid; i < EE; i += 128) { float x = row[i]; ss += x*x; }
    #pragma unroll
    for (int o = 16; o; o >>= 1) ss += __shfl_xor_sync(0xffffffffu, ss, o);
    __shared__ float wred[4];
    if (lane == 0) wred[wp] = ss;
    __syncthreads();
    if (tid == 0) g_invnorm[tb] = 1.0f / sqrtf(wred[0]+wred[1]+wred[2]+wred[3]);

    __shared__ float s_lin[64];
    for (int i = 0; i < 16; i++) {
        int co = wp*16 + i;
        int n = co & 3, h = (co >> 2) & 7, r = co >> 5;
        float s = 0.f;
        const float* x = row + h*DD;
        const float* w = hw + ((r*HH + h)*DD)*4 + n;
        for (int d = lane; d < DD; d += 32) s += x[d] * w[d*4];
        #pragma unroll
        for (int o = 16; o; o >>= 1) s += __shfl_xor_sync(0xffffffffu, s, o);
        if (lane == 0) s_lin[co] = s;
    }
    __syncthreads();
    if (tid < 16) {
        int r = tid >> 3, h = tid & 7;
        const float* L = s_lin + (r*8 + h)*4;
        float best = L[0]; int bi = 0;
        #pragma unroll
        for (int j = 1; j < 8; j++) {
            float v = (j < 4) ? L[j] : -L[j-4];
            if (v > best) { best = v; bi = j; }
        }
        g_hash[((b*RR + r)*HH + h)*TT + t] = bi;
    }
}

// ==================== stable counting sort ====================
__global__ void __launch_bounds__(256) sort_kernel()
{
    int brh = blockIdx.x;
    const int* hs = g_hash + brh*TT;
    int* pp = g_perm + brh*TT;
    int* iv = g_inv  + brh*TT;
    __shared__ int hist[256][8];
    __shared__ int binbase[8];
    int tid = threadIdx.x;
    int base = tid*8;
    int myh[8];
    int loc[8] = {0,0,0,0,0,0,0,0};
    #pragma unroll
    for (int i = 0; i < 8; i++) { int v = hs[base+i]; myh[i] = v; loc[v]++; }
    #pragma unroll
    for (int v = 0; v < 8; v++) hist[tid][v] = loc[v];
    __syncthreads();
    if (tid < 8) {
        int s = 0;
        for (int j = 0; j < 256; j++) { int c = hist[j][tid]; hist[j][tid] = s; s += c; }
        binbase[tid] = s;
    }
    __syncthreads();
    if (tid == 0) {
        int s = 0;
        for (int v = 0; v < 8; v++) { int t0 = binbase[v]; binbase[v] = s; s += t0; }
    }
    __syncthreads();
    int off[8];
    #pragma unroll
    for (int v = 0; v < 8; v++) off[v] = binbase[v] + hist[tid][v];
    #pragma unroll
    for (int i = 0; i < 8; i++) {
        int v = myh[i];
        int pos = off[v]++;
        pp[pos] = base + i;
        iv[base + i] = pos;
    }
}

// ==================== chunked LSH attention (register-tiled) ====================
// 256 threads = 8 warps; warp w owns q rows w*4 .. w*4+3.
// smem rows padded to 132 floats (16B-aligned, conflict-free float4).
#define QS_STRIDE 132
#define PS_STRIDE 100
#define ATTN_SMEM_FLOATS (32*QS_STRIDE + 96*QS_STRIDE + 96*QS_STRIDE + 32*PS_STRIDE)

__global__ void __launch_bounds__(256) attn_kernel()
{
    extern __shared__ float sm[];
    float* q_s = sm;                         // 32 x 132
    float* k_s = sm + 32*QS_STRIDE;          // 96 x 132
    float* v_s = k_s + 96*QS_STRIDE;         // 96 x 132
    float* p_s = v_s + 96*QS_STRIDE;         // 32 x 100
    __shared__ int s_qid[32], s_kid[96], s_qh[32], s_kh[96];
    __shared__ int s_cq[64], s_ck[192];
    __shared__ float s_kinv[96];

    int bid = blockIdx.x;
    int c = bid & 63;
    int h = (bid >> 6) & 7;
    int r = (bid >> 9) & 1;
    int b = bid >> 10;
    int brh = (b*RR + r)*HH + h;
    const int* pp = g_perm + brh*TT;
    int tid = threadIdx.x, lane = tid & 31, wp = tid >> 5;

    if (tid < 32) {
        int qid = pp[c*32 + tid];
        s_qid[tid] = qid;
        s_qh[tid] = g_hash[brh*TT + qid];
        s_cq[tid*2+0] = g_inv[((b*RR+0)*HH+h)*TT + qid] >> 5;
        s_cq[tid*2+1] = g_inv[((b*RR+1)*HH+h)*TT + qid] >> 5;
    }
    if (tid < 96) {
        int cc = (c + (tid >> 5) + CC - 1) & (CC - 1);
        int kid = pp[cc*32 + (tid & 31)];
        s_kid[tid] = kid;
        s_kh[tid] = g_hash[brh*TT + kid];
        s_kinv[tid] = g_invnorm[kid*BB + b];
        s_ck[tid*2+0] = g_inv[((b*RR+0)*HH+h)*TT + kid] >> 5;
        s_ck[tid*2+1] = g_inv[((b*RR+1)*HH+h)*TT + kid] >> 5;
    }
    __syncthreads();

    const float scale = 0.08838834764831845f;  // 128^-0.5
    // q tile: 32 rows x 128 d = 1024 float4
    for (int idx = tid; idx < 32*32; idx += 256) {
        int l = idx >> 5, d4 = idx & 31;
        float4 v4 = *(const float4*)&g_qf[(s_qid[l]*BB + b)*EE + h*DD + d4*4];
        v4.x *= scale; v4.y *= scale; v4.z *= scale; v4.w *= scale;
        *(float4*)&q_s[l*QS_STRIDE + d4*4] = v4;
    }
    // k/v tiles: 96 rows x 128 d
    for (int idx = tid; idx < 96*32; idx += 256) {
        int j = idx >> 5, d4 = idx & 31;
        size_t gbase = (size_t)(s_kid[j]*BB + b)*EE + h*DD + d4*4;
        float4 kq = *(const float4*)&g_qf[gbase];
        float4 vv = *(const float4*)&g_vf[gbase];
        float kin = s_kinv[j];
        kq.x *= kin; kq.y *= kin; kq.z *= kin; kq.w *= kin;
        *(float4*)&k_s[j*QS_STRIDE + d4*4] = kq;
        *(float4*)&v_s[j*QS_STRIDE + d4*4] = vv;
    }
    __syncthreads();

    const int l0 = wp*4;

    // ---------- QK^T : acc[i][mi], i = q-row, key m = mi*32 + lane
    float acc[4][3] = {};
    {
        const float* kp0 = k_s + lane*QS_STRIDE;
        const float* kp1 = k_s + (lane+32)*QS_STRIDE;
        const float* kp2 = k_s + (lane+64)*QS_STRIDE;
        #pragma unroll 4
        for (int d4 = 0; d4 < 32; d4++) {
            float4 k0 = *(const float4*)(kp0 + d4*4);
            float4 k1 = *(const float4*)(kp1 + d4*4);
            float4 k2 = *(const float4*)(kp2 + d4*4);
            #pragma unroll
            for (int i = 0; i < 4; i++) {
                float4 qv = *(const float4*)&q_s[(l0+i)*QS_STRIDE + d4*4];
                acc[i][0] += qv.x*k0.x; acc[i][0] += qv.y*k0.y;
                acc[i][0] += qv.z*k0.z; acc[i][0] += qv.w*k0.w;
                acc[i][1] += qv.x*k1.x; acc[i][1] += qv.y*k1.y;
                acc[i][1] += qv.z*k1.z; acc[i][1] += qv.w*k1.w;
                acc[i][2] += qv.x*k2.x; acc[i][2] += qv.y*k2.y;
                acc[i][2] += qv.z*k2.z; acc[i][2] += qv.w*k2.w;
            }
        }
    }

    // ---------- masks + dup correction + softmax; write p/rowsum into p_s
    {
        int kh[3], kid[3], ck0[3], ck1[3];
        #pragma unroll
        for (int mi = 0; mi < 3; mi++) {
            int m = mi*32 + lane;
            kh[mi] = s_kh[m]; kid[mi] = s_kid[m];
            ck0[mi] = s_ck[m*2+0]; ck1[mi] = s_ck[m*2+1];
        }
        #pragma unroll
        for (int i = 0; i < 4; i++) {
            int row = l0 + i;
            int qh = s_qh[row], qid = s_qid[row];
            int cq0 = s_cq[row*2], cq1 = s_cq[row*2+1];
            #pragma unroll
            for (int mi = 0; mi < 3; mi++) {
                float s = acc[i][mi];
                if (qh != kh[mi])   s -= 1.0e16f;
                if (qid == kid[mi]) s -= 1.0e8f;
                int d0 = (ck0[mi] - cq0) & (CC-1);
                int d1 = (ck1[mi] - cq1) & (CC-1);
                int dup = ((d0 <= 1) | (d0 == CC-1)) + ((d1 <= 1) | (d1 == CC-1));
                if (dup == 2) s -= 0.6931471805599453f;
                acc[i][mi] = s;
            }
            float mx = fmaxf(acc[i][0], fmaxf(acc[i][1], acc[i][2]));
            #pragma unroll
            for (int o = 16; o; o >>= 1) mx = fmaxf(mx, __shfl_xor_sync(0xffffffffu, mx, o));
            float p0 = expf(acc[i][0]-mx), p1 = expf(acc[i][1]-mx), p2 = expf(acc[i][2]-mx);
            float sum = p0 + p1 + p2;
            #pragma unroll
            for (int o = 16; o; o >>= 1) sum += __shfl_xor_sync(0xffffffffu, sum, o);
            float rinv = 1.0f / sum;
            p_s[row*PS_STRIDE + lane]      = p0*rinv;
            p_s[row*PS_STRIDE + 32 + lane] = p1*rinv;
            p_s[row*PS_STRIDE + 64 + lane] = p2*rinv;
            if (lane == 0) g_z[((r*BB + b)*HH + h)*TT + qid] = logf(sum) + mx;
        }
    }
    __syncwarp();

    // ---------- P @ V : lane owns d-range [lane*4, lane*4+4)
    float o0x[4], o0y[4], o0z[4], o0w[4];
    #pragma unroll
    for (int i = 0; i < 4; i++) { o0x[i]=0.f; o0y[i]=0.f; o0z[i]=0.f; o0w[i]=0.f; }
    {
        const int dbase = lane*4;
        #pragma unroll 4
        for (int m4 = 0; m4 < 24; m4++) {
            float4 v0 = *(const float4*)&v_s[(m4*4+0)*QS_STRIDE + dbase];
            float4 v1 = *(const float4*)&v_s[(m4*4+1)*QS_STRIDE + dbase];
            float4 v2 = *(const float4*)&v_s[(m4*4+2)*QS_STRIDE + dbase];
            float4 v3 = *(const float4*)&v_s[(m4*4+3)*QS_STRIDE + dbase];
            #pragma unroll
            for (int i = 0; i < 4; i++) {
                float4 pv = *(const float4*)&p_s[(l0+i)*PS_STRIDE + m4*4];
                o0x[i] += pv.x*v0.x; o0y[i] += pv.x*v0.y; o0z[i] += pv.x*v0.z; o0w[i] += pv.x*v0.w;
                o0x[i] += pv.y*v1.x; o0y[i] += pv.y*v1.y; o0z[i] += pv.y*v1.z; o0w[i] += pv.y*v1.w;
                o0x[i] += pv.z*v2.x; o0y[i] += pv.z*v2.y; o0z[i] += pv.z*v2.z; o0w[i] += pv.z*v2.w;
                o0x[i] += pv.w*v3.x; o0y[i] += pv.w*v3.y; o0z[i] += pv.w*v3.z; o0w[i] += pv.w*v3.w;
            }
        }
        #pragma unroll
        for (int i = 0; i < 4; i++) {
            int qid = s_qid[l0+i];
            float* op = g_o + ((size_t)((r*BB + b)*HH + h)*TT + qid)*DD + dbase;
            *(float4*)op = make_float4(o0x[i], o0y[i], o0z[i], o0w[i]);
        }
    }
}

// ==================== round combination ====================
__global__ void __launch_bounds__(256) combine_kernel()
{
    int idx = blockIdx.x*256 + threadIdx.x;
    int d = idx & 127;
    int t = (idx >> 7) & 2047;
    int h = (idx >> 18) & 7;
    int b = idx >> 21;
    int zi = (b*HH + h)*TT + t;
    float z0 = g_z[zi];
    float z1 = g_z[BB*HH*TT + zi];
    float mz = fmaxf(z0, z1);
    float e0 = expf(z0 - mz), e1 = expf(z1 - mz);
    float winv = 1.0f / (e0 + e1);
    int oi = ((b*HH + h)*TT + t)*DD + d;
    float o0 = g_o[oi];
    float o1 = g_o[BB*HH*TT*DD + oi];
    g_ctx[(t*BB + b)*EE + h*DD + d] = (e0*o0 + e1*o1) * winv;
}

// ==================== launch ====================
extern "C" void kernel_launch(void* const* d_in, const int* in_sizes, int n_in,
                              void* d_out, int out_size)
{
    const float* query = (const float*)d_in[0];
    const float* value = (const float*)d_in[2];
    const float* Wq = (const float*)d_in[3];
    const float* bq = (const float*)d_in[4];
    const float* Wv = (const float*)d_in[5];
    const float* bv = (const float*)d_in[6];
    const float* Wo = (const float*)d_in[7];
    const float* bo = (const float*)d_in[8];
    const float* hw = (const float*)d_in[9];

    float* qf;  cudaGetSymbolAddress((void**)&qf,  g_qf);
    float* vf;  cudaGetSymbolAddress((void**)&vf,  g_vf);
    float* ctx; cudaGetSymbolAddress((void**)&ctx, g_ctx);

    const int ATTN_SMEM = ATTN_SMEM_FLOATS * (int)sizeof(float);  // 131072 B
    cudaFuncSetAttribute(attn_kernel, cudaFuncAttributeMaxDynamicSharedMemorySize, ATTN_SMEM);

    dim3 gqv(NTOT/128, (TT*BB)/128, 2);   // fused Wq + Wv projections
    dim3 go (NTOT/128, (TT*BB)/128, 1);   // Wo projection

    sgemm_kernel<<<gqv, 256>>>(query, Wq, bq, qf, value, Wv, bv, vf);
    norm_hash_kernel<<<TT*BB, 128>>>(hw);
    sort_kernel<<<BB*RR*HH, 256>>>();
    attn_kernel<<<BB*RR*HH*CC, 256, ATTN_SMEM>>>();
    combine_kernel<<<(BB*HH*TT*DD)/256, 256>>>();
    sgemm_kernel<<<go, 256>>>(ctx, Wo, bo, (float*)d_out,
                              ctx, Wo, bo, (float*)d_out);
}